// round 1
// baseline (speedup 1.0000x reference)
#include <cuda_runtime.h>
#include <math.h>

// Problem constants
#define DIMK   1024
#define HEADS  16
#define BLK    129
#define DHEAD  64
#define BATCH  4
#define NB     32
#define NLEN   (BLK*NB)        // 4128
#define ROWS   (BATCH*NLEN)    // 16512
#define QKV_LD 3072            // q|k|v concatenated per row

// Scratch (no allocations allowed)
__device__ float g_qkv[(size_t)ROWS * QKV_LD]; // ~203 MB
__device__ float g_att[(size_t)ROWS * DIMK];   // ~65 MB

// ---------------------------------------------------------------------------
// SGEMM: C[m, ng+n] = sum_k A[m,k] * W[n,k]   (A and W both K-major row-major)
// Tile 128x128, BK=16, 256 threads, 8x8 per thread.
// W selected per 1024-column group (for fused QKV). Optional bias on epilogue.
// ---------------------------------------------------------------------------
__global__ __launch_bounds__(256) void sgemm_kernel(
    const float* __restrict__ A,
    const float* __restrict__ W0, const float* __restrict__ W1,
    const float* __restrict__ W2,
    float* __restrict__ C, int ldc, const float* __restrict__ bias)
{
    __shared__ float As[16][132];
    __shared__ float Bs[16][132];

    const int m0 = blockIdx.x * 128;
    const int ng = blockIdx.y * 128;
    const float* W = (ng >= 2048) ? W2 : (ng >= 1024 ? W1 : W0);
    const int n0 = ng & 1023;

    const int t  = threadIdx.x;
    const int tm = t >> 4;      // 0..15 over M
    const int tn = t & 15;      // 0..15 over N

    float acc[8][8];
#pragma unroll
    for (int i = 0; i < 8; i++)
#pragma unroll
        for (int j = 0; j < 8; j++) acc[i][j] = 0.f;

    for (int k0 = 0; k0 < DIMK; k0 += 16) {
#pragma unroll
        for (int i = 0; i < 2; i++) {
            int idx = t + i * 256;          // 0..511 float4 slots
            int r   = idx >> 2;             // 0..127 tile row
            int c4  = (idx & 3) << 2;       // 0,4,8,12
            float4 fa = *(const float4*)(A + (size_t)(m0 + r) * DIMK + k0 + c4);
            As[c4+0][r] = fa.x; As[c4+1][r] = fa.y;
            As[c4+2][r] = fa.z; As[c4+3][r] = fa.w;
            float4 fb = *(const float4*)(W + (size_t)(n0 + r) * DIMK + k0 + c4);
            Bs[c4+0][r] = fb.x; Bs[c4+1][r] = fb.y;
            Bs[c4+2][r] = fb.z; Bs[c4+3][r] = fb.w;
        }
        __syncthreads();

#pragma unroll
        for (int k = 0; k < 16; k++) {
            float a[8], b[8];
            *(float4*)&a[0] = *(const float4*)&As[k][tm*8];
            *(float4*)&a[4] = *(const float4*)&As[k][tm*8+4];
            *(float4*)&b[0] = *(const float4*)&Bs[k][tn*8];
            *(float4*)&b[4] = *(const float4*)&Bs[k][tn*8+4];
#pragma unroll
            for (int i = 0; i < 8; i++)
#pragma unroll
                for (int j = 0; j < 8; j++)
                    acc[i][j] += a[i] * b[j];
        }
        __syncthreads();
    }

#pragma unroll
    for (int i = 0; i < 8; i++) {
        int m = m0 + tm*8 + i;
        float* crow = C + (size_t)m * ldc + ng + tn*8;
#pragma unroll
        for (int j = 0; j < 8; j += 4) {
            float4 o;
            o.x = acc[i][j+0]; o.y = acc[i][j+1];
            o.z = acc[i][j+2]; o.w = acc[i][j+3];
            if (bias) {
                const float* bp = bias + ng + tn*8 + j;
                o.x += bp[0]; o.y += bp[1]; o.z += bp[2]; o.w += bp[3];
            }
            *(float4*)(crow + j) = o;
        }
    }
}

// ---------------------------------------------------------------------------
// Block-local attention: one CTA per (b, blk, h). 160 threads.
// K,V staged in dynamic smem (2 * 129 * 64 floats = 66048 B).
// Thread tid < 129 owns query row tid; scores in a 129-entry local array.
// ---------------------------------------------------------------------------
__global__ __launch_bounds__(160) void attn_kernel()
{
    extern __shared__ float sm[];
    float* Ks = sm;
    float* Vs = sm + BLK * DHEAD;

    const int bid = blockIdx.x;
    const int h   = bid & 15;
    const int blk = (bid >> 4) & 31;
    const int b   = bid >> 9;

    const size_t rowbase = (size_t)b * NLEN + (size_t)blk * BLK;
    const float* base = g_qkv + rowbase * QKV_LD + h * DHEAD;
    const int tid = threadIdx.x;

    for (int idx = tid; idx < BLK * 16; idx += 160) {
        int j = idx >> 4, c = idx & 15;
        const float* p = base + (size_t)j * QKV_LD + c * 4;
        *(float4*)(Ks + j*64 + c*4) = *(const float4*)(p + 1024);
        *(float4*)(Vs + j*64 + c*4) = *(const float4*)(p + 2048);
    }
    __syncthreads();

    if (tid < BLK) {
        const float* qp = base + (size_t)tid * QKV_LD;
        float q[64];
#pragma unroll
        for (int c = 0; c < 16; c++) {
            float4 f = *(const float4*)(qp + c*4);
            q[c*4+0]=f.x; q[c*4+1]=f.y; q[c*4+2]=f.z; q[c*4+3]=f.w;
        }

        float s[BLK];
        float mmax = -1e30f;
        for (int j = 0; j < BLK; j++) {
            const float* kj = Ks + j * 64;
            float a0=0.f, a1=0.f, a2=0.f, a3=0.f;
#pragma unroll
            for (int d = 0; d < 64; d += 4) {
                a0 += q[d+0] * kj[d+0];
                a1 += q[d+1] * kj[d+1];
                a2 += q[d+2] * kj[d+2];
                a3 += q[d+3] * kj[d+3];
            }
            float sv = ((a0 + a1) + (a2 + a3)) * 0.125f;  // 1/sqrt(64)
            s[j] = sv;
            mmax = fmaxf(mmax, sv);
        }

        float l = 0.f;
        for (int j = 0; j < BLK; j++) {
            float p = __expf(s[j] - mmax);
            s[j] = p;
            l += p;
        }
        float inv = 1.f / l;

        float acc[64];
#pragma unroll
        for (int d = 0; d < 64; d++) acc[d] = 0.f;
        for (int j = 0; j < BLK; j++) {
            float p = s[j];
            const float* vj = Vs + j * 64;
#pragma unroll
            for (int d = 0; d < 64; d++) acc[d] += p * vj[d];
        }

        float* op = g_att + (rowbase + tid) * DIMK + h * DHEAD;
#pragma unroll
        for (int c = 0; c < 16; c++) {
            float4 f;
            f.x = acc[c*4+0]*inv; f.y = acc[c*4+1]*inv;
            f.z = acc[c*4+2]*inv; f.w = acc[c*4+3]*inv;
            *(float4*)(op + c*4) = f;
        }
    }
}

// ---------------------------------------------------------------------------
// Global leader attention: one CTA per (b, h). Queries/keys/values are the
// pos-0 token of each of the 32 blocks. Adds into g_att (after attn_kernel).
// ---------------------------------------------------------------------------
__global__ __launch_bounds__(64) void gattn_kernel()
{
    __shared__ float Kg[NB * 64];
    __shared__ float Vg[NB * 64];

    const int b = blockIdx.x >> 4;
    const int h = blockIdx.x & 15;
    const int tid = threadIdx.x;

    const float* base = g_qkv + (size_t)b * NLEN * QKV_LD + h * DHEAD;

    for (int idx = tid; idx < NB * 16; idx += 64) {
        int j = idx >> 4, c = idx & 15;
        const float* p = base + (size_t)j * BLK * QKV_LD + c * 4;
        *(float4*)(Kg + j*64 + c*4) = *(const float4*)(p + 1024);
        *(float4*)(Vg + j*64 + c*4) = *(const float4*)(p + 2048);
    }
    __syncthreads();

    if (tid < NB) {
        const float* qp = base + (size_t)tid * BLK * QKV_LD;
        float q[64];
#pragma unroll
        for (int c = 0; c < 16; c++) {
            float4 f = *(const float4*)(qp + c*4);
            q[c*4+0]=f.x; q[c*4+1]=f.y; q[c*4+2]=f.z; q[c*4+3]=f.w;
        }

        float s[NB];
        float mmax = -1e30f;
#pragma unroll
        for (int j = 0; j < NB; j++) {
            const float* kj = Kg + j * 64;
            float a0=0.f, a1=0.f, a2=0.f, a3=0.f;
#pragma unroll
            for (int d = 0; d < 64; d += 4) {
                a0 += q[d+0]*kj[d+0]; a1 += q[d+1]*kj[d+1];
                a2 += q[d+2]*kj[d+2]; a3 += q[d+3]*kj[d+3];
            }
            float sv = ((a0+a1)+(a2+a3)) * 0.125f;
            s[j] = sv;
            mmax = fmaxf(mmax, sv);
        }
        float l = 0.f;
#pragma unroll
        for (int j = 0; j < NB; j++) { s[j] = __expf(s[j]-mmax); l += s[j]; }
        float inv = 1.f / l;

        float acc[64];
#pragma unroll
        for (int d = 0; d < 64; d++) acc[d] = 0.f;
#pragma unroll
        for (int j = 0; j < NB; j++) {
            float p = s[j];
            const float* vj = Vg + j * 64;
#pragma unroll
            for (int d = 0; d < 64; d++) acc[d] += p * vj[d];
        }

        float* op = g_att + ((size_t)b * NLEN + (size_t)tid * BLK) * DIMK + h * DHEAD;
#pragma unroll
        for (int d = 0; d < 64; d++) op[d] += acc[d] * inv;
    }
}

// ---------------------------------------------------------------------------
extern "C" void kernel_launch(void* const* d_in, const int* in_sizes, int n_in,
                              void* d_out, int out_size)
{
    (void)in_sizes; (void)n_in; (void)out_size;
    const float* x  = (const float*)d_in[0];
    const float* Wq = (const float*)d_in[1];
    const float* Wk = (const float*)d_in[2];
    const float* Wv = (const float*)d_in[3];
    const float* Wo = (const float*)d_in[4];
    const float* bo = (const float*)d_in[5];
    float* out = (float*)d_out;

    float* qkv; cudaGetSymbolAddress((void**)&qkv, g_qkv);
    float* att; cudaGetSymbolAddress((void**)&att, g_att);

    // 1) fused QKV projection: (16512 x 1024) @ [Wq;Wk;Wv]^T -> (16512 x 3072)
    {
        dim3 grid(ROWS / 128, QKV_LD / 128);   // 129 x 24
        sgemm_kernel<<<grid, 256>>>(x, Wq, Wk, Wv, qkv, QKV_LD, nullptr);
    }

    // 2) block-local attention
    {
        const int smem = 2 * BLK * DHEAD * (int)sizeof(float);  // 66048 B
        cudaFuncSetAttribute(attn_kernel,
                             cudaFuncAttributeMaxDynamicSharedMemorySize, smem);
        attn_kernel<<<BATCH * NB * HEADS, 160, smem>>>();
    }

    // 3) global leader attention (adds into pos-0 rows)
    gattn_kernel<<<BATCH * HEADS, 64>>>();

    // 4) output projection + bias
    {
        dim3 grid(ROWS / 128, DIMK / 128);     // 129 x 8
        sgemm_kernel<<<grid, 256>>>(att, Wo, Wo, Wo, out, DIMK, bo);
    }
}

// round 6
// speedup vs baseline: 1.9987x; 1.9987x over previous
#include <cuda_runtime.h>
#include <cuda_bf16.h>
#include <math.h>
#include <stdint.h>

// Problem constants
#define DIMK   1024
#define HEADS  16
#define BLK    129
#define DHEAD  64
#define BATCH  4
#define NB     32
#define NLEN   (BLK*NB)        // 4128
#define ROWS   (BATCH*NLEN)    // 16512
#define QKV_LD 3072

// Scratch (no allocations allowed)
__device__ float g_qkv[(size_t)ROWS * QKV_LD];
__device__ float g_att[(size_t)ROWS * DIMK];
__device__ __nv_bfloat16 g_xh[(size_t)ROWS * DIMK];
__device__ __nv_bfloat16 g_xl[(size_t)ROWS * DIMK];
__device__ __nv_bfloat16 g_wh[(size_t)QKV_LD * DIMK];
__device__ __nv_bfloat16 g_wl[(size_t)QKV_LD * DIMK];
__device__ __nv_bfloat16 g_woh[(size_t)DIMK * DIMK];
__device__ __nv_bfloat16 g_wol[(size_t)DIMK * DIMK];
__device__ __nv_bfloat16 g_ath[(size_t)ROWS * DIMK];
__device__ __nv_bfloat16 g_atl[(size_t)ROWS * DIMK];

// ---------------------------------------------------------------------------
// helpers
// ---------------------------------------------------------------------------
__device__ __forceinline__ uint32_t smem_u32(const void* p) {
    uint32_t a;
    asm("{ .reg .u64 t; cvta.to.shared.u64 t, %1; cvt.u32.u64 %0, t; }"
        : "=r"(a) : "l"(p));
    return a;
}
__device__ __forceinline__ void cp16(uint32_t saddr, const void* gptr) {
    asm volatile("cp.async.cg.shared.global [%0], [%1], 16;"
                 :: "r"(saddr), "l"(gptr));
}
__device__ __forceinline__ void cp_commit() {
    asm volatile("cp.async.commit_group;");
}
template <int N>
__device__ __forceinline__ void cp_wait() {
    asm volatile("cp.async.wait_group %0;" :: "n"(N));
}
__device__ __forceinline__ void ldm4(uint32_t* r, uint32_t addr) {
    asm volatile("ldmatrix.sync.aligned.m8n8.x4.shared.b16 {%0,%1,%2,%3}, [%4];"
                 : "=r"(r[0]), "=r"(r[1]), "=r"(r[2]), "=r"(r[3]) : "r"(addr));
}
__device__ __forceinline__ void mma16816(float* d, const uint32_t* a,
                                         uint32_t b0, uint32_t b1) {
    asm volatile(
        "mma.sync.aligned.m16n8k16.row.col.f32.bf16.bf16.f32 "
        "{%0,%1,%2,%3}, {%4,%5,%6,%7}, {%8,%9}, {%0,%1,%2,%3};"
        : "+f"(d[0]), "+f"(d[1]), "+f"(d[2]), "+f"(d[3])
        : "r"(a[0]), "r"(a[1]), "r"(a[2]), "r"(a[3]), "r"(b0), "r"(b1));
}

// ---------------------------------------------------------------------------
// fp32 -> (bf16 hi, bf16 lo) split conversion
// ---------------------------------------------------------------------------
__global__ __launch_bounds__(256) void cvt_kernel(
    const float* __restrict__ src, __nv_bfloat16* __restrict__ hi,
    __nv_bfloat16* __restrict__ lo, int n4)
{
    int i = blockIdx.x * 256 + threadIdx.x;
    if (i >= n4) return;
    float4 f = ((const float4*)src)[i];
    __nv_bfloat16 h0 = __float2bfloat16(f.x);
    __nv_bfloat16 h1 = __float2bfloat16(f.y);
    __nv_bfloat16 h2 = __float2bfloat16(f.z);
    __nv_bfloat16 h3 = __float2bfloat16(f.w);
    __nv_bfloat16 l0 = __float2bfloat16(f.x - __bfloat162float(h0));
    __nv_bfloat16 l1 = __float2bfloat16(f.y - __bfloat162float(h1));
    __nv_bfloat16 l2 = __float2bfloat16(f.z - __bfloat162float(h2));
    __nv_bfloat16 l3 = __float2bfloat16(f.w - __bfloat162float(h3));
    __nv_bfloat162 hp0(h0, h1), hp1(h2, h3), lp0(l0, l1), lp1(l2, l3);
    uint2 hv, lv;
    hv.x = *(uint32_t*)&hp0; hv.y = *(uint32_t*)&hp1;
    lv.x = *(uint32_t*)&lp0; lv.y = *(uint32_t*)&lp1;
    ((uint2*)hi)[i] = hv;
    ((uint2*)lo)[i] = lv;
}

// ---------------------------------------------------------------------------
// Split-bf16 warp-MMA GEMM: C[m,n] = sum_k A[m,k]*B[n,k]
// CTA tile 128x128, BK=32, 2-stage cp.async pipeline, 8 warps (2x4),
// warp tile 64x32, mma.m16n8k16, 3 MMAs per tile-step (AhBh+AhBl+AlBh).
// ---------------------------------------------------------------------------
#define ASTR   80            // smem row stride bytes (32 bf16 + pad)
#define ABUF   (128*ASTR)    // 10240 B per operand buffer
#define STAGE  (4*ABUF)      // 40960 B per stage
#define NCH    (DIMK/32)     // 32 chunks

__global__ __launch_bounds__(256, 1) void gemm_bf16x3(
    const __nv_bfloat16* __restrict__ Ah, const __nv_bfloat16* __restrict__ Al,
    const __nv_bfloat16* __restrict__ Bh, const __nv_bfloat16* __restrict__ Bl,
    float* __restrict__ C, int ldc, const float* __restrict__ bias)
{
    extern __shared__ char smem[];
    const uint32_t sb = smem_u32(smem);
    const int t = threadIdx.x;
    const int m0 = blockIdx.x * 128;
    const int n0 = blockIdx.y * 128;

    const int lane = t & 31;
    const int w    = t >> 5;
    const int wm   = w & 1;       // 2 M-warps
    const int wn   = w >> 1;      // 4 N-warps

    const __nv_bfloat16* gsrc[4] = {
        Ah + (size_t)m0 * DIMK, Al + (size_t)m0 * DIMK,
        Bh + (size_t)n0 * DIMK, Bl + (size_t)n0 * DIMK };

    // per-thread cp.async assignment: 8 segments of 16B per chunk
    const int seg_row = (t & 511) >> 2;        // reused pattern below
    (void)seg_row;

    auto load_chunk = [&](int c) {
        const int k0 = c * 32;
        const uint32_t stg = sb + (uint32_t)(c & 1) * STAGE;
#pragma unroll
        for (int pass = 0; pass < 8; pass++) {
            int seg = pass * 256 + t;          // 0..2047
            int buf = seg >> 9;                // 0..3
            int idx = seg & 511;
            int row = idx >> 2;                // 0..127
            int c16 = idx & 3;                 // 0..3
            const void* g = gsrc[buf] + (size_t)row * DIMK + k0 + c16 * 8;
            cp16(stg + buf * ABUF + row * ASTR + c16 * 16, g);
        }
        cp_commit();
    };

    // per-lane ldmatrix offsets (bytes)
    const uint32_t a_off = (uint32_t)((lane & 15) * ASTR + (lane >> 4) * 16);
    const uint32_t b_off = (uint32_t)(((lane & 7) + ((lane >> 4) << 3)) * ASTR
                                      + (((lane >> 3) & 1) << 4));

    float acc[4][4][4];
#pragma unroll
    for (int i = 0; i < 4; i++)
#pragma unroll
        for (int j = 0; j < 4; j++)
#pragma unroll
            for (int r = 0; r < 4; r++) acc[i][j][r] = 0.f;

    load_chunk(0);

    for (int c = 0; c < NCH; c++) {
        if (c + 1 < NCH) {
            load_chunk(c + 1);
            cp_wait<1>();
        } else {
            cp_wait<0>();
        }
        __syncthreads();

        const uint32_t stg = sb + (uint32_t)(c & 1) * STAGE;
        const uint32_t aH = stg + 0 * ABUF + (uint32_t)(wm * 64) * ASTR + a_off;
        const uint32_t aL = stg + 1 * ABUF + (uint32_t)(wm * 64) * ASTR + a_off;
        const uint32_t bH = stg + 2 * ABUF + (uint32_t)(wn * 32) * ASTR + b_off;
        const uint32_t bL = stg + 3 * ABUF + (uint32_t)(wn * 32) * ASTR + b_off;

#pragma unroll
        for (int ks = 0; ks < 2; ks++) {
            const uint32_t ko = (uint32_t)(ks * 32);   // 16 bf16 = 32 bytes
            uint32_t ah[4][4], al[4][4];
#pragma unroll
            for (int mt = 0; mt < 4; mt++) {
                ldm4(ah[mt], aH + (uint32_t)(mt * 16) * ASTR + ko);
                ldm4(al[mt], aL + (uint32_t)(mt * 16) * ASTR + ko);
            }
            uint32_t bh[2][4], bl[2][4];
#pragma unroll
            for (int np = 0; np < 2; np++) {
                ldm4(bh[np], bH + (uint32_t)(np * 16) * ASTR + ko);
                ldm4(bl[np], bL + (uint32_t)(np * 16) * ASTR + ko);
            }
#pragma unroll
            for (int mt = 0; mt < 4; mt++) {
#pragma unroll
                for (int nt = 0; nt < 4; nt++) {
                    const uint32_t* ph = &bh[nt >> 1][(nt & 1) * 2];
                    const uint32_t* pl = &bl[nt >> 1][(nt & 1) * 2];
                    mma16816(acc[mt][nt], ah[mt], ph[0], ph[1]);
                    mma16816(acc[mt][nt], ah[mt], pl[0], pl[1]);
                    mma16816(acc[mt][nt], al[mt], ph[0], ph[1]);
                }
            }
        }
        __syncthreads();
    }

    // epilogue
    const int g  = lane >> 2;
    const int tg = lane & 3;
#pragma unroll
    for (int mt = 0; mt < 4; mt++) {
        const int m = m0 + wm * 64 + mt * 16 + g;
#pragma unroll
        for (int nt = 0; nt < 4; nt++) {
            const int n = n0 + wn * 32 + nt * 8 + tg * 2;
            float b0 = 0.f, b1 = 0.f;
            if (bias) { b0 = bias[n]; b1 = bias[n + 1]; }
            float2 v0, v1;
            v0.x = acc[mt][nt][0] + b0; v0.y = acc[mt][nt][1] + b1;
            v1.x = acc[mt][nt][2] + b0; v1.y = acc[mt][nt][3] + b1;
            *(float2*)(C + (size_t)m * ldc + n) = v0;
            *(float2*)(C + (size_t)(m + 8) * ldc + n) = v1;
        }
    }
}

// ---------------------------------------------------------------------------
// Block-local attention: one CTA per (b, blk, h). 160 threads.
// ---------------------------------------------------------------------------
__global__ __launch_bounds__(160) void attn_kernel()
{
    extern __shared__ float sm[];
    float* Ks = sm;
    float* Vs = sm + BLK * DHEAD;

    const int bid = blockIdx.x;
    const int h   = bid & 15;
    const int blk = (bid >> 4) & 31;
    const int b   = bid >> 9;

    const size_t rowbase = (size_t)b * NLEN + (size_t)blk * BLK;
    const float* base = g_qkv + rowbase * QKV_LD + h * DHEAD;
    const int tid = threadIdx.x;

    for (int idx = tid; idx < BLK * 16; idx += 160) {
        int j = idx >> 4, c = idx & 15;
        const float* p = base + (size_t)j * QKV_LD + c * 4;
        *(float4*)(Ks + j*64 + c*4) = *(const float4*)(p + 1024);
        *(float4*)(Vs + j*64 + c*4) = *(const float4*)(p + 2048);
    }
    __syncthreads();

    if (tid < BLK) {
        const float* qp = base + (size_t)tid * QKV_LD;
        float q[64];
#pragma unroll
        for (int c = 0; c < 16; c++) {
            float4 f = *(const float4*)(qp + c*4);
            q[c*4+0]=f.x; q[c*4+1]=f.y; q[c*4+2]=f.z; q[c*4+3]=f.w;
        }

        float s[BLK];
        float mmax = -1e30f;
        for (int j = 0; j < BLK; j++) {
            const float* kj = Ks + j * 64;
            float a0=0.f, a1=0.f, a2=0.f, a3=0.f;
#pragma unroll
            for (int d = 0; d < 64; d += 4) {
                a0 += q[d+0] * kj[d+0];
                a1 += q[d+1] * kj[d+1];
                a2 += q[d+2] * kj[d+2];
                a3 += q[d+3] * kj[d+3];
            }
            float sv = ((a0 + a1) + (a2 + a3)) * 0.125f;
            s[j] = sv;
            mmax = fmaxf(mmax, sv);
        }

        float l = 0.f;
        for (int j = 0; j < BLK; j++) {
            float p = __expf(s[j] - mmax);
            s[j] = p;
            l += p;
        }
        float inv = 1.f / l;

        float acc[64];
#pragma unroll
        for (int d = 0; d < 64; d++) acc[d] = 0.f;
        for (int j = 0; j < BLK; j++) {
            float p = s[j];
            const float* vj = Vs + j * 64;
#pragma unroll
            for (int d = 0; d < 64; d++) acc[d] += p * vj[d];
        }

        float* op = g_att + (rowbase + tid) * DIMK + h * DHEAD;
#pragma unroll
        for (int c = 0; c < 16; c++) {
            float4 f;
            f.x = acc[c*4+0]*inv; f.y = acc[c*4+1]*inv;
            f.z = acc[c*4+2]*inv; f.w = acc[c*4+3]*inv;
            *(float4*)(op + c*4) = f;
        }
    }
}

// ---------------------------------------------------------------------------
// Global leader attention
// ---------------------------------------------------------------------------
__global__ __launch_bounds__(64) void gattn_kernel()
{
    __shared__ float Kg[NB * 64];
    __shared__ float Vg[NB * 64];

    const int b = blockIdx.x >> 4;
    const int h = blockIdx.x & 15;
    const int tid = threadIdx.x;

    const float* base = g_qkv + (size_t)b * NLEN * QKV_LD + h * DHEAD;

    for (int idx = tid; idx < NB * 16; idx += 64) {
        int j = idx >> 4, c = idx & 15;
        const float* p = base + (size_t)j * BLK * QKV_LD + c * 4;
        *(float4*)(Kg + j*64 + c*4) = *(const float4*)(p + 1024);
        *(float4*)(Vg + j*64 + c*4) = *(const float4*)(p + 2048);
    }
    __syncthreads();

    if (tid < NB) {
        const float* qp = base + (size_t)tid * BLK * QKV_LD;
        float q[64];
#pragma unroll
        for (int c = 0; c < 16; c++) {
            float4 f = *(const float4*)(qp + c*4);
            q[c*4+0]=f.x; q[c*4+1]=f.y; q[c*4+2]=f.z; q[c*4+3]=f.w;
        }

        float s[NB];
        float mmax = -1e30f;
#pragma unroll
        for (int j = 0; j < NB; j++) {
            const float* kj = Kg + j * 64;
            float a0=0.f, a1=0.f, a2=0.f, a3=0.f;
#pragma unroll
            for (int d = 0; d < 64; d += 4) {
                a0 += q[d+0]*kj[d+0]; a1 += q[d+1]*kj[d+1];
                a2 += q[d+2]*kj[d+2]; a3 += q[d+3]*kj[d+3];
            }
            float sv = ((a0+a1)+(a2+a3)) * 0.125f;
            s[j] = sv;
            mmax = fmaxf(mmax, sv);
        }
        float l = 0.f;
#pragma unroll
        for (int j = 0; j < NB; j++) { s[j] = __expf(s[j]-mmax); l += s[j]; }
        float inv = 1.f / l;

        float acc[64];
#pragma unroll
        for (int d = 0; d < 64; d++) acc[d] = 0.f;
#pragma unroll
        for (int j = 0; j < NB; j++) {
            float p = s[j];
            const float* vj = Vg + j * 64;
#pragma unroll
            for (int d = 0; d < 64; d++) acc[d] += p * vj[d];
        }

        float* op = g_att + ((size_t)b * NLEN + (size_t)tid * BLK) * DIMK + h * DHEAD;
#pragma unroll
        for (int d = 0; d < 64; d++) op[d] += acc[d] * inv;
    }
}

// ---------------------------------------------------------------------------
extern "C" void kernel_launch(void* const* d_in, const int* in_sizes, int n_in,
                              void* d_out, int out_size)
{
    (void)in_sizes; (void)n_in; (void)out_size;
    const float* x  = (const float*)d_in[0];
    const float* Wq = (const float*)d_in[1];
    const float* Wk = (const float*)d_in[2];
    const float* Wv = (const float*)d_in[3];
    const float* Wo = (const float*)d_in[4];
    const float* bo = (const float*)d_in[5];
    float* out = (float*)d_out;

    float *qkv, *att;
    __nv_bfloat16 *xh, *xl, *wh, *wl, *woh, *wol, *ath, *atl;
    cudaGetSymbolAddress((void**)&qkv, g_qkv);
    cudaGetSymbolAddress((void**)&att, g_att);
    cudaGetSymbolAddress((void**)&xh, g_xh);
    cudaGetSymbolAddress((void**)&xl, g_xl);
    cudaGetSymbolAddress((void**)&wh, g_wh);
    cudaGetSymbolAddress((void**)&wl, g_wl);
    cudaGetSymbolAddress((void**)&woh, g_woh);
    cudaGetSymbolAddress((void**)&wol, g_wol);
    cudaGetSymbolAddress((void**)&ath, g_ath);
    cudaGetSymbolAddress((void**)&atl, g_atl);

    static int s_init = 0;
    if (!s_init) {
        cudaFuncSetAttribute(gemm_bf16x3,
            cudaFuncAttributeMaxDynamicSharedMemorySize, 2 * STAGE);
        cudaFuncSetAttribute(attn_kernel,
            cudaFuncAttributeMaxDynamicSharedMemorySize,
            2 * BLK * DHEAD * (int)sizeof(float));
        s_init = 1;
    }

    // fp32 -> bf16 hi/lo splits
    {
        int n4x = ROWS * DIMK / 4;
        cvt_kernel<<<n4x / 256, 256>>>(x, xh, xl, n4x);
        int n4w = DIMK * DIMK / 4;
        cvt_kernel<<<n4w / 256, 256>>>(Wq, wh, wl, n4w);
        cvt_kernel<<<n4w / 256, 256>>>(Wk, wh + (size_t)1024 * DIMK,
                                       wl + (size_t)1024 * DIMK, n4w);
        cvt_kernel<<<n4w / 256, 256>>>(Wv, wh + (size_t)2048 * DIMK,
                                       wl + (size_t)2048 * DIMK, n4w);
        cvt_kernel<<<n4w / 256, 256>>>(Wo, woh, wol, n4w);
    }

    // 1) QKV projection: (16512 x 1024) x (3072 x 1024)^T
    {
        dim3 grid(ROWS / 128, QKV_LD / 128);   // 129 x 24
        gemm_bf16x3<<<grid, 256, 2 * STAGE>>>(xh, xl, wh, wl, qkv, QKV_LD, nullptr);
    }

    // 2) block-local attention
    {
        const int smem = 2 * BLK * DHEAD * (int)sizeof(float);
        attn_kernel<<<BATCH * NB * HEADS, 160, smem>>>();
    }

    // 3) global leader attention
    gattn_kernel<<<BATCH * HEADS, 64>>>();

    // 4) split attention output, then output projection + bias
    {
        int n4 = ROWS * DIMK / 4;
        cvt_kernel<<<n4 / 256, 256>>>(att, ath, atl, n4);
        dim3 grid(ROWS / 128, DIMK / 128);     // 129 x 8
        gemm_bf16x3<<<grid, 256, 2 * STAGE>>>(ath, atl, woh, wol, out, DIMK, bo);
    }
}

// round 8
// speedup vs baseline: 2.3078x; 1.1547x over previous
#include <cuda_runtime.h>
#include <cuda_bf16.h>
#include <math.h>
#include <stdint.h>

// Problem constants
#define DIMK   1024
#define HEADS  16
#define BLK    129
#define DHEAD  64
#define BATCH  4
#define NB     32
#define NLEN   (BLK*NB)        // 4128
#define ROWS   (BATCH*NLEN)    // 16512
#define QKV_LD 3072

// Scratch (no allocations allowed)
__device__ float g_qkv[(size_t)ROWS * QKV_LD];
__device__ float g_gout[(size_t)BATCH * HEADS * NB * DHEAD];   // global-attn out
__device__ __nv_bfloat16 g_xh[(size_t)ROWS * DIMK];
__device__ __nv_bfloat16 g_xl[(size_t)ROWS * DIMK];
__device__ __nv_bfloat16 g_wh[(size_t)QKV_LD * DIMK];
__device__ __nv_bfloat16 g_wl[(size_t)QKV_LD * DIMK];
__device__ __nv_bfloat16 g_woh[(size_t)DIMK * DIMK];
__device__ __nv_bfloat16 g_wol[(size_t)DIMK * DIMK];
__device__ __nv_bfloat16 g_ath[(size_t)ROWS * DIMK];
__device__ __nv_bfloat16 g_atl[(size_t)ROWS * DIMK];

// ---------------------------------------------------------------------------
// helpers
// ---------------------------------------------------------------------------
__device__ __forceinline__ uint32_t smem_u32(const void* p) {
    uint32_t a;
    asm("{ .reg .u64 t; cvta.to.shared.u64 t, %1; cvt.u32.u64 %0, t; }"
        : "=r"(a) : "l"(p));
    return a;
}
__device__ __forceinline__ void cp16(uint32_t saddr, const void* gptr) {
    asm volatile("cp.async.cg.shared.global [%0], [%1], 16;"
                 :: "r"(saddr), "l"(gptr));
}
__device__ __forceinline__ void cp_commit() {
    asm volatile("cp.async.commit_group;");
}
template <int N>
__device__ __forceinline__ void cp_wait() {
    asm volatile("cp.async.wait_group %0;" :: "n"(N));
}
__device__ __forceinline__ void ldm4(uint32_t* r, uint32_t addr) {
    asm volatile("ldmatrix.sync.aligned.m8n8.x4.shared.b16 {%0,%1,%2,%3}, [%4];"
                 : "=r"(r[0]), "=r"(r[1]), "=r"(r[2]), "=r"(r[3]) : "r"(addr));
}
__device__ __forceinline__ void mma16816(float* d, const uint32_t* a,
                                         uint32_t b0, uint32_t b1) {
    asm volatile(
        "mma.sync.aligned.m16n8k16.row.col.f32.bf16.bf16.f32 "
        "{%0,%1,%2,%3}, {%4,%5,%6,%7}, {%8,%9}, {%0,%1,%2,%3};"
        : "+f"(d[0]), "+f"(d[1]), "+f"(d[2]), "+f"(d[3])
        : "r"(a[0]), "r"(a[1]), "r"(a[2]), "r"(a[3]), "r"(b0), "r"(b1));
}
__device__ __forceinline__ void split2(float f, __nv_bfloat16& h, __nv_bfloat16& l) {
    h = __float2bfloat16(f);
    l = __float2bfloat16(f - __bfloat162float(h));
}

// ---------------------------------------------------------------------------
// fp32 -> (bf16 hi, bf16 lo) split conversion, 4 float4 per thread (MLP=4)
// ---------------------------------------------------------------------------
__global__ __launch_bounds__(256) void cvt_kernel(
    const float* __restrict__ src, __nv_bfloat16* __restrict__ hi,
    __nv_bfloat16* __restrict__ lo, int n4)
{
    int i0 = (blockIdx.x * 256 + threadIdx.x) * 4;
    float4 f[4];
#pragma unroll
    for (int u = 0; u < 4; u++)
        if (i0 + u < n4) f[u] = ((const float4*)src)[i0 + u];
#pragma unroll
    for (int u = 0; u < 4; u++) {
        if (i0 + u >= n4) break;
        __nv_bfloat16 h0, h1, h2, h3, l0, l1, l2, l3;
        split2(f[u].x, h0, l0); split2(f[u].y, h1, l1);
        split2(f[u].z, h2, l2); split2(f[u].w, h3, l3);
        __nv_bfloat162 hp0(h0, h1), hp1(h2, h3), lp0(l0, l1), lp1(l2, l3);
        uint2 hv, lv;
        hv.x = *(uint32_t*)&hp0; hv.y = *(uint32_t*)&hp1;
        lv.x = *(uint32_t*)&lp0; lv.y = *(uint32_t*)&lp1;
        ((uint2*)hi)[i0 + u] = hv;
        ((uint2*)lo)[i0 + u] = lv;
    }
}

// ---------------------------------------------------------------------------
// Split-bf16 warp-MMA GEMM (unchanged from round 6)
// ---------------------------------------------------------------------------
#define ASTR   80
#define ABUF   (128*ASTR)
#define STAGE  (4*ABUF)
#define NCH    (DIMK/32)

__global__ __launch_bounds__(256, 1) void gemm_bf16x3(
    const __nv_bfloat16* __restrict__ Ah, const __nv_bfloat16* __restrict__ Al,
    const __nv_bfloat16* __restrict__ Bh, const __nv_bfloat16* __restrict__ Bl,
    float* __restrict__ C, int ldc, const float* __restrict__ bias)
{
    extern __shared__ char smem[];
    const uint32_t sb = smem_u32(smem);
    const int t = threadIdx.x;
    const int m0 = blockIdx.x * 128;
    const int n0 = blockIdx.y * 128;

    const int lane = t & 31;
    const int w    = t >> 5;
    const int wm   = w & 1;
    const int wn   = w >> 1;

    const __nv_bfloat16* gsrc[4] = {
        Ah + (size_t)m0 * DIMK, Al + (size_t)m0 * DIMK,
        Bh + (size_t)n0 * DIMK, Bl + (size_t)n0 * DIMK };

    auto load_chunk = [&](int c) {
        const int k0 = c * 32;
        const uint32_t stg = sb + (uint32_t)(c & 1) * STAGE;
#pragma unroll
        for (int pass = 0; pass < 8; pass++) {
            int seg = pass * 256 + t;
            int buf = seg >> 9;
            int idx = seg & 511;
            int row = idx >> 2;
            int c16 = idx & 3;
            const void* g = gsrc[buf] + (size_t)row * DIMK + k0 + c16 * 8;
            cp16(stg + buf * ABUF + row * ASTR + c16 * 16, g);
        }
        cp_commit();
    };

    const uint32_t a_off = (uint32_t)((lane & 15) * ASTR + (lane >> 4) * 16);
    const uint32_t b_off = (uint32_t)(((lane & 7) + ((lane >> 4) << 3)) * ASTR
                                      + (((lane >> 3) & 1) << 4));

    float acc[4][4][4];
#pragma unroll
    for (int i = 0; i < 4; i++)
#pragma unroll
        for (int j = 0; j < 4; j++)
#pragma unroll
            for (int r = 0; r < 4; r++) acc[i][j][r] = 0.f;

    load_chunk(0);

    for (int c = 0; c < NCH; c++) {
        if (c + 1 < NCH) {
            load_chunk(c + 1);
            cp_wait<1>();
        } else {
            cp_wait<0>();
        }
        __syncthreads();

        const uint32_t stg = sb + (uint32_t)(c & 1) * STAGE;
        const uint32_t aH = stg + 0 * ABUF + (uint32_t)(wm * 64) * ASTR + a_off;
        const uint32_t aL = stg + 1 * ABUF + (uint32_t)(wm * 64) * ASTR + a_off;
        const uint32_t bH = stg + 2 * ABUF + (uint32_t)(wn * 32) * ASTR + b_off;
        const uint32_t bL = stg + 3 * ABUF + (uint32_t)(wn * 32) * ASTR + b_off;

#pragma unroll
        for (int ks = 0; ks < 2; ks++) {
            const uint32_t ko = (uint32_t)(ks * 32);
            uint32_t ah[4][4], al[4][4];
#pragma unroll
            for (int mt = 0; mt < 4; mt++) {
                ldm4(ah[mt], aH + (uint32_t)(mt * 16) * ASTR + ko);
                ldm4(al[mt], aL + (uint32_t)(mt * 16) * ASTR + ko);
            }
            uint32_t bh[2][4], bl[2][4];
#pragma unroll
            for (int np = 0; np < 2; np++) {
                ldm4(bh[np], bH + (uint32_t)(np * 16) * ASTR + ko);
                ldm4(bl[np], bL + (uint32_t)(np * 16) * ASTR + ko);
            }
#pragma unroll
            for (int mt = 0; mt < 4; mt++) {
#pragma unroll
                for (int nt = 0; nt < 4; nt++) {
                    const uint32_t* ph = &bh[nt >> 1][(nt & 1) * 2];
                    const uint32_t* pl = &bl[nt >> 1][(nt & 1) * 2];
                    mma16816(acc[mt][nt], ah[mt], ph[0], ph[1]);
                    mma16816(acc[mt][nt], ah[mt], pl[0], pl[1]);
                    mma16816(acc[mt][nt], al[mt], ph[0], ph[1]);
                }
            }
        }
        __syncthreads();
    }

    const int g  = lane >> 2;
    const int tg = lane & 3;
#pragma unroll
    for (int mt = 0; mt < 4; mt++) {
        const int m = m0 + wm * 64 + mt * 16 + g;
#pragma unroll
        for (int nt = 0; nt < 4; nt++) {
            const int n = n0 + wn * 32 + nt * 8 + tg * 2;
            float b0 = 0.f, b1 = 0.f;
            if (bias) { b0 = bias[n]; b1 = bias[n + 1]; }
            float2 v0, v1;
            v0.x = acc[mt][nt][0] + b0; v0.y = acc[mt][nt][1] + b1;
            v1.x = acc[mt][nt][2] + b0; v1.y = acc[mt][nt][3] + b1;
            *(float2*)(C + (size_t)m * ldc + n) = v0;
            *(float2*)(C + (size_t)(m + 8) * ldc + n) = v1;
        }
    }
}

// ---------------------------------------------------------------------------
// Tensor-core block attention: one CTA per (b, blk, h), 9 warps (288 thr).
// S = Q@K^T (split bf16, 3 terms) -> fragment softmax -> P bf16 hi/lo ->
// O = P@V (split, 3 terms) -> /l (+global add on row0) -> split to ath/atl.
// ---------------------------------------------------------------------------
// smem layout (bytes)
#define QKSTR   144                 // 72 bf16 cols (64 data + pad)
#define VPSTR   304                 // 152 bf16 cols (144 data + pad)
#define AQH     0
#define AQL     20736               // 144*144
#define AKH     41472
#define AKL     62208
#define AVH     82944               // V^T: 64 rows x 304B
#define AVL     102400
#define APH     121856              // P: 144 rows x 304B
#define APL     165632
#define ALSUM   209408              // 144 floats
#define ATT_SMEM 209984

__global__ __launch_bounds__(288, 1) void attn_mma_kernel()
{
    extern __shared__ char smem[];
    const uint32_t sb = smem_u32(smem);
    const int tid = threadIdx.x;

    const int bid = blockIdx.x;
    const int h   = bid & 15;
    const int blk = (bid >> 4) & 31;
    const int b   = bid >> 9;
    const size_t rowbase = (size_t)b * NLEN + (size_t)blk * BLK;
    const float* base = g_qkv + rowbase * QKV_LD + h * DHEAD;

    // zero pad rows 129..143 of Q/K hi+lo (36 words per row)
    for (int i = tid; i < 15 * 36; i += 288) {
        uint32_t off = (uint32_t)(129 + i / 36) * QKSTR + (uint32_t)(i % 36) * 4;
        *(uint32_t*)(smem + AQH + off) = 0;
        *(uint32_t*)(smem + AQL + off) = 0;
        *(uint32_t*)(smem + AKH + off) = 0;
        *(uint32_t*)(smem + AKL + off) = 0;
    }
    // zero V^T token cols 129..143
    for (int i = tid; i < 64 * 15; i += 288) {
        uint32_t off = (uint32_t)(i / 15) * VPSTR + (uint32_t)(129 + i % 15) * 2;
        *(__nv_bfloat16*)(smem + AVH + off) = __float2bfloat16(0.f);
        *(__nv_bfloat16*)(smem + AVL + off) = __float2bfloat16(0.f);
    }

    // load + split Q (x0.125), K, V^T
    for (int idx = tid; idx < BLK * 16; idx += 288) {
        const int j = idx >> 4, c = idx & 15;
        const float* p = base + (size_t)j * QKV_LD + c * 4;
        float4 q = *(const float4*)(p);
        float4 k = *(const float4*)(p + 1024);
        float4 v = *(const float4*)(p + 2048);
        q.x *= 0.125f; q.y *= 0.125f; q.z *= 0.125f; q.w *= 0.125f;
        __nv_bfloat16 qh[4], ql[4], kh[4], kl[4];
        split2(q.x, qh[0], ql[0]); split2(q.y, qh[1], ql[1]);
        split2(q.z, qh[2], ql[2]); split2(q.w, qh[3], ql[3]);
        split2(k.x, kh[0], kl[0]); split2(k.y, kh[1], kl[1]);
        split2(k.z, kh[2], kl[2]); split2(k.w, kh[3], kl[3]);
        uint32_t qrow = (uint32_t)j * QKSTR + (uint32_t)c * 8;
        *(__nv_bfloat162*)(smem + AQH + qrow)     = __nv_bfloat162(qh[0], qh[1]);
        *(__nv_bfloat162*)(smem + AQH + qrow + 4) = __nv_bfloat162(qh[2], qh[3]);
        *(__nv_bfloat162*)(smem + AQL + qrow)     = __nv_bfloat162(ql[0], ql[1]);
        *(__nv_bfloat162*)(smem + AQL + qrow + 4) = __nv_bfloat162(ql[2], ql[3]);
        *(__nv_bfloat162*)(smem + AKH + qrow)     = __nv_bfloat162(kh[0], kh[1]);
        *(__nv_bfloat162*)(smem + AKH + qrow + 4) = __nv_bfloat162(kh[2], kh[3]);
        *(__nv_bfloat162*)(smem + AKL + qrow)     = __nv_bfloat162(kl[0], kl[1]);
        *(__nv_bfloat162*)(smem + AKL + qrow + 4) = __nv_bfloat162(kl[2], kl[3]);
        // V transposed: Vt[d][token j]
        float vv[4] = {v.x, v.y, v.z, v.w};
#pragma unroll
        for (int e = 0; e < 4; e++) {
            __nv_bfloat16 vh, vl;
            split2(vv[e], vh, vl);
            uint32_t off = (uint32_t)(c * 4 + e) * VPSTR + (uint32_t)j * 2;
            *(__nv_bfloat16*)(smem + AVH + off) = vh;
            *(__nv_bfloat16*)(smem + AVL + off) = vl;
        }
    }
    __syncthreads();

    const int w    = tid >> 5;      // 0..8 = m-tile
    const int lane = tid & 31;
    const int tg   = lane & 3;
    const int gr   = lane >> 2;

    // ---- S = Q@K^T over full N=144 ----
    float acc[18][4];
#pragma unroll
    for (int i = 0; i < 18; i++)
#pragma unroll
        for (int r = 0; r < 4; r++) acc[i][r] = 0.f;

    const uint32_t aoff = (uint32_t)((lane & 15) * QKSTR + (lane >> 4) * 16)
                        + (uint32_t)(w * 16) * QKSTR;
    const uint32_t bro  = (uint32_t)((lane & 7) + ((lane >> 4) << 3));
    const uint32_t bko  = (uint32_t)(((lane >> 3) & 1) << 4);

#pragma unroll
    for (int ko = 0; ko < 4; ko++) {
        uint32_t ah[4], al[4];
        ldm4(ah, sb + AQH + aoff + ko * 32);
        ldm4(al, sb + AQL + aoff + ko * 32);
#pragma unroll
        for (int np = 0; np < 9; np++) {
            uint32_t boff = ((uint32_t)(np * 16) + bro) * QKSTR + bko + ko * 32;
            uint32_t bh[4], bl[4];
            ldm4(bh, sb + AKH + boff);
            ldm4(bl, sb + AKL + boff);
#pragma unroll
            for (int q2 = 0; q2 < 2; q2++) {
                float* a0 = acc[np * 2 + q2];
                mma16816(a0, ah, bh[q2 * 2], bh[q2 * 2 + 1]);
                mma16816(a0, ah, bl[q2 * 2], bl[q2 * 2 + 1]);
                mma16816(a0, al, bh[q2 * 2], bh[q2 * 2 + 1]);
            }
        }
    }

    // ---- fragment softmax (rows owned entirely by this warp) ----
    const int r0 = w * 16 + gr;
    const int r1 = r0 + 8;
    float m0 = -1e30f, m1 = -1e30f;
#pragma unroll
    for (int nt = 0; nt < 18; nt++) {
        int col = nt * 8 + tg * 2;
        if (col < 129)     { m0 = fmaxf(m0, acc[nt][0]); m1 = fmaxf(m1, acc[nt][2]); }
        if (col + 1 < 129) { m0 = fmaxf(m0, acc[nt][1]); m1 = fmaxf(m1, acc[nt][3]); }
    }
    m0 = fmaxf(m0, __shfl_xor_sync(0xffffffff, m0, 1));
    m0 = fmaxf(m0, __shfl_xor_sync(0xffffffff, m0, 2));
    m1 = fmaxf(m1, __shfl_xor_sync(0xffffffff, m1, 1));
    m1 = fmaxf(m1, __shfl_xor_sync(0xffffffff, m1, 2));

    float l0 = 0.f, l1 = 0.f;
#pragma unroll
    for (int nt = 0; nt < 18; nt++) {
        int col = nt * 8 + tg * 2;
        acc[nt][0] = (col < 129)     ? __expf(acc[nt][0] - m0) : 0.f;
        acc[nt][1] = (col + 1 < 129) ? __expf(acc[nt][1] - m0) : 0.f;
        acc[nt][2] = (col < 129)     ? __expf(acc[nt][2] - m1) : 0.f;
        acc[nt][3] = (col + 1 < 129) ? __expf(acc[nt][3] - m1) : 0.f;
        l0 += acc[nt][0] + acc[nt][1];
        l1 += acc[nt][2] + acc[nt][3];
    }
    l0 += __shfl_xor_sync(0xffffffff, l0, 1);
    l0 += __shfl_xor_sync(0xffffffff, l0, 2);
    l1 += __shfl_xor_sync(0xffffffff, l1, 1);
    l1 += __shfl_xor_sync(0xffffffff, l1, 2);
    if (tg == 0) {
        *(float*)(smem + ALSUM + r0 * 4) = l0;
        *(float*)(smem + ALSUM + r1 * 4) = l1;
    }

    // write P (hi/lo) to smem
#pragma unroll
    for (int nt = 0; nt < 18; nt++) {
        int col = nt * 8 + tg * 2;
        __nv_bfloat16 h0, h1, h2, h3, e0, e1, e2, e3;
        split2(acc[nt][0], h0, e0); split2(acc[nt][1], h1, e1);
        split2(acc[nt][2], h2, e2); split2(acc[nt][3], h3, e3);
        uint32_t o0 = (uint32_t)r0 * VPSTR + (uint32_t)col * 2;
        uint32_t o1 = (uint32_t)r1 * VPSTR + (uint32_t)col * 2;
        *(__nv_bfloat162*)(smem + APH + o0) = __nv_bfloat162(h0, h1);
        *(__nv_bfloat162*)(smem + APH + o1) = __nv_bfloat162(h2, h3);
        *(__nv_bfloat162*)(smem + APL + o0) = __nv_bfloat162(e0, e1);
        *(__nv_bfloat162*)(smem + APL + o1) = __nv_bfloat162(e2, e3);
    }
    __syncwarp();

    // ---- O = P@V (N = 64) ----
    float o[8][4];
#pragma unroll
    for (int i = 0; i < 8; i++)
#pragma unroll
        for (int r = 0; r < 4; r++) o[i][r] = 0.f;

    const uint32_t paoff = (uint32_t)((lane & 15) * VPSTR + (lane >> 4) * 16)
                         + (uint32_t)(w * 16) * VPSTR;
#pragma unroll
    for (int ko = 0; ko < 9; ko++) {
        uint32_t ph[4], pl[4];
        ldm4(ph, sb + APH + paoff + ko * 32);
        ldm4(pl, sb + APL + paoff + ko * 32);
#pragma unroll
        for (int np = 0; np < 4; np++) {
            uint32_t boff = ((uint32_t)(np * 16) + bro) * VPSTR + bko + ko * 32;
            uint32_t vh[4], vl[4];
            ldm4(vh, sb + AVH + boff);
            ldm4(vl, sb + AVL + boff);
#pragma unroll
            for (int q2 = 0; q2 < 2; q2++) {
                float* d0 = o[np * 2 + q2];
                mma16816(d0, ph, vh[q2 * 2], vh[q2 * 2 + 1]);
                mma16816(d0, ph, vl[q2 * 2], vl[q2 * 2 + 1]);
                mma16816(d0, pl, vh[q2 * 2], vh[q2 * 2 + 1]);
            }
        }
    }

    // ---- epilogue: /l, +global on row 0, split to g_ath/g_atl ----
    const float* gadd = g_gout + ((size_t)(b * 16 + h) * 32 + blk) * 64;
    const float inv0 = 1.f / *(float*)(smem + ALSUM + r0 * 4);
    const float inv1 = 1.f / *(float*)(smem + ALSUM + r1 * 4);
#pragma unroll
    for (int nt = 0; nt < 8; nt++) {
        int col = nt * 8 + tg * 2;
        if (r0 < 129) {
            float v0 = o[nt][0] * inv0;
            float v1 = o[nt][1] * inv0;
            if (r0 == 0) { v0 += gadd[col]; v1 += gadd[col + 1]; }
            __nv_bfloat16 h0, h1, e0, e1;
            split2(v0, h0, e0); split2(v1, h1, e1);
            size_t go = (rowbase + r0) * DIMK + h * DHEAD + col;
            *(__nv_bfloat162*)(g_ath + go) = __nv_bfloat162(h0, h1);
            *(__nv_bfloat162*)(g_atl + go) = __nv_bfloat162(e0, e1);
        }
        if (r1 < 129) {
            float v0 = o[nt][2] * inv1;
            float v1 = o[nt][3] * inv1;
            __nv_bfloat16 h0, h1, e0, e1;
            split2(v0, h0, e0); split2(v1, h1, e1);
            size_t go = (rowbase + r1) * DIMK + h * DHEAD + col;
            *(__nv_bfloat162*)(g_ath + go) = __nv_bfloat162(h0, h1);
            *(__nv_bfloat162*)(g_atl + go) = __nv_bfloat162(e0, e1);
        }
    }
}

// ---------------------------------------------------------------------------
// Global leader attention: writes g_gout (runs BEFORE attn_mma_kernel)
// ---------------------------------------------------------------------------
__global__ __launch_bounds__(64) void gattn_kernel()
{
    __shared__ float Kg[NB * 64];
    __shared__ float Vg[NB * 64];

    const int b = blockIdx.x >> 4;
    const int h = blockIdx.x & 15;
    const int tid = threadIdx.x;

    const float* base = g_qkv + (size_t)b * NLEN * QKV_LD + h * DHEAD;

    for (int idx = tid; idx < NB * 16; idx += 64) {
        int j = idx >> 4, c = idx & 15;
        const float* p = base + (size_t)j * BLK * QKV_LD + c * 4;
        *(float4*)(Kg + j*64 + c*4) = *(const float4*)(p + 1024);
        *(float4*)(Vg + j*64 + c*4) = *(const float4*)(p + 2048);
    }
    __syncthreads();

    if (tid < NB) {
        const float* qp = base + (size_t)tid * BLK * QKV_LD;
        float q[64];
#pragma unroll
        for (int c = 0; c < 16; c++) {
            float4 f = *(const float4*)(qp + c*4);
            q[c*4+0]=f.x; q[c*4+1]=f.y; q[c*4+2]=f.z; q[c*4+3]=f.w;
        }

        float s[NB];
        float mmax = -1e30f;
#pragma unroll
        for (int j = 0; j < NB; j++) {
            const float* kj = Kg + j * 64;
            float a0=0.f, a1=0.f, a2=0.f, a3=0.f;
#pragma unroll
            for (int d = 0; d < 64; d += 4) {
                a0 += q[d+0]*kj[d+0]; a1 += q[d+1]*kj[d+1];
                a2 += q[d+2]*kj[d+2]; a3 += q[d+3]*kj[d+3];
            }
            float sv = ((a0+a1)+(a2+a3)) * 0.125f;
            s[j] = sv;
            mmax = fmaxf(mmax, sv);
        }
        float l = 0.f;
#pragma unroll
        for (int j = 0; j < NB; j++) { s[j] = __expf(s[j]-mmax); l += s[j]; }
        float inv = 1.f / l;

        float acc[64];
#pragma unroll
        for (int d = 0; d < 64; d++) acc[d] = 0.f;
#pragma unroll
        for (int j = 0; j < NB; j++) {
            float p = s[j];
            const float* vj = Vg + j * 64;
#pragma unroll
            for (int d = 0; d < 64; d++) acc[d] += p * vj[d];
        }

        float* op = g_gout + ((size_t)(b * 16 + h) * 32 + tid) * 64;
#pragma unroll
        for (int d = 0; d < 64; d++) op[d] = acc[d] * inv;
    }
}

// ---------------------------------------------------------------------------
extern "C" void kernel_launch(void* const* d_in, const int* in_sizes, int n_in,
                              void* d_out, int out_size)
{
    (void)in_sizes; (void)n_in; (void)out_size;
    const float* x  = (const float*)d_in[0];
    const float* Wq = (const float*)d_in[1];
    const float* Wk = (const float*)d_in[2];
    const float* Wv = (const float*)d_in[3];
    const float* Wo = (const float*)d_in[4];
    const float* bo = (const float*)d_in[5];
    float* out = (float*)d_out;

    float* qkv;
    __nv_bfloat16 *xh, *xl, *wh, *wl, *woh, *wol, *ath, *atl;
    cudaGetSymbolAddress((void**)&qkv, g_qkv);
    cudaGetSymbolAddress((void**)&xh, g_xh);
    cudaGetSymbolAddress((void**)&xl, g_xl);
    cudaGetSymbolAddress((void**)&wh, g_wh);
    cudaGetSymbolAddress((void**)&wl, g_wl);
    cudaGetSymbolAddress((void**)&woh, g_woh);
    cudaGetSymbolAddress((void**)&wol, g_wol);
    cudaGetSymbolAddress((void**)&ath, g_ath);
    cudaGetSymbolAddress((void**)&atl, g_atl);

    static int s_init = 0;
    if (!s_init) {
        cudaFuncSetAttribute(gemm_bf16x3,
            cudaFuncAttributeMaxDynamicSharedMemorySize, 2 * STAGE);
        cudaFuncSetAttribute(attn_mma_kernel,
            cudaFuncAttributeMaxDynamicSharedMemorySize, ATT_SMEM);
        s_init = 1;
    }

    // fp32 -> bf16 hi/lo splits
    {
        int n4x = ROWS * DIMK / 4;
        cvt_kernel<<<(n4x + 1023) / 1024, 256>>>(x, xh, xl, n4x);
        int n4w = DIMK * DIMK / 4;
        cvt_kernel<<<(n4w + 1023) / 1024, 256>>>(Wq, wh, wl, n4w);
        cvt_kernel<<<(n4w + 1023) / 1024, 256>>>(Wk, wh + (size_t)1024 * DIMK,
                                                 wl + (size_t)1024 * DIMK, n4w);
        cvt_kernel<<<(n4w + 1023) / 1024, 256>>>(Wv, wh + (size_t)2048 * DIMK,
                                                 wl + (size_t)2048 * DIMK, n4w);
        cvt_kernel<<<(n4w + 1023) / 1024, 256>>>(Wo, woh, wol, n4w);
    }

    // 1) QKV projection
    {
        dim3 grid(ROWS / 128, QKV_LD / 128);
        gemm_bf16x3<<<grid, 256, 2 * STAGE>>>(xh, xl, wh, wl, qkv, QKV_LD, nullptr);
    }

    // 2) global leader attention (before block attention)
    gattn_kernel<<<BATCH * HEADS, 64>>>();

    // 3) block-local attention (tensor cores), writes split bf16 directly
    attn_mma_kernel<<<BATCH * NB * HEADS, 288, ATT_SMEM>>>();

    // 4) output projection + bias
    {
        dim3 grid(ROWS / 128, DIMK / 128);
        gemm_bf16x3<<<grid, 256, 2 * STAGE>>>(ath, atl, woh, wol, out, DIMK, bo);
    }
}

// round 10
// speedup vs baseline: 2.6464x; 1.1467x over previous
#include <cuda_runtime.h>
#include <cuda_bf16.h>
#include <math.h>
#include <stdint.h>

// Problem constants
#define DIMK   1024
#define HEADS  16
#define BLK    129
#define DHEAD  64
#define BATCH  4
#define NB     32
#define NLEN   (BLK*NB)        // 4128
#define ROWS   (BATCH*NLEN)    // 16512
#define QKV_LD 3072

// Scratch (no allocations allowed)
__device__ float g_qkv[(size_t)ROWS * QKV_LD];
__device__ float g_gout[(size_t)BATCH * HEADS * NB * DHEAD];   // global-attn out
__device__ __nv_bfloat16 g_xh[(size_t)ROWS * DIMK];
__device__ __nv_bfloat16 g_xl[(size_t)ROWS * DIMK];
__device__ __nv_bfloat16 g_wh[(size_t)QKV_LD * DIMK];
__device__ __nv_bfloat16 g_wl[(size_t)QKV_LD * DIMK];
__device__ __nv_bfloat16 g_woh[(size_t)DIMK * DIMK];
__device__ __nv_bfloat16 g_wol[(size_t)DIMK * DIMK];
__device__ __nv_bfloat16 g_ath[(size_t)ROWS * DIMK];
__device__ __nv_bfloat16 g_atl[(size_t)ROWS * DIMK];

// ---------------------------------------------------------------------------
// helpers
// ---------------------------------------------------------------------------
__device__ __forceinline__ uint32_t smem_u32(const void* p) {
    uint32_t a;
    asm("{ .reg .u64 t; cvta.to.shared.u64 t, %1; cvt.u32.u64 %0, t; }"
        : "=r"(a) : "l"(p));
    return a;
}
__device__ __forceinline__ void cp16(uint32_t saddr, const void* gptr) {
    asm volatile("cp.async.cg.shared.global [%0], [%1], 16;"
                 :: "r"(saddr), "l"(gptr));
}
__device__ __forceinline__ void cp_commit() {
    asm volatile("cp.async.commit_group;");
}
template <int N>
__device__ __forceinline__ void cp_wait() {
    asm volatile("cp.async.wait_group %0;" :: "n"(N));
}
__device__ __forceinline__ void ldm4(uint32_t* r, uint32_t addr) {
    asm volatile("ldmatrix.sync.aligned.m8n8.x4.shared.b16 {%0,%1,%2,%3}, [%4];"
                 : "=r"(r[0]), "=r"(r[1]), "=r"(r[2]), "=r"(r[3]) : "r"(addr));
}
__device__ __forceinline__ void mma16816(float* d, const uint32_t* a,
                                         uint32_t b0, uint32_t b1) {
    asm volatile(
        "mma.sync.aligned.m16n8k16.row.col.f32.bf16.bf16.f32 "
        "{%0,%1,%2,%3}, {%4,%5,%6,%7}, {%8,%9}, {%0,%1,%2,%3};"
        : "+f"(d[0]), "+f"(d[1]), "+f"(d[2]), "+f"(d[3])
        : "r"(a[0]), "r"(a[1]), "r"(a[2]), "r"(a[3]), "r"(b0), "r"(b1));
}
__device__ __forceinline__ void split2(float f, __nv_bfloat16& h, __nv_bfloat16& l) {
    h = __float2bfloat16(f);
    l = __float2bfloat16(f - __bfloat162float(h));
}

// ---------------------------------------------------------------------------
// fp32 -> (bf16 hi, bf16 lo) split conversion, 4 float4 per thread (MLP=4)
// ---------------------------------------------------------------------------
__global__ __launch_bounds__(256) void cvt_kernel(
    const float* __restrict__ src, __nv_bfloat16* __restrict__ hi,
    __nv_bfloat16* __restrict__ lo, int n4)
{
    int i0 = (blockIdx.x * 256 + threadIdx.x) * 4;
    float4 f[4];
#pragma unroll
    for (int u = 0; u < 4; u++)
        if (i0 + u < n4) f[u] = ((const float4*)src)[i0 + u];
#pragma unroll
    for (int u = 0; u < 4; u++) {
        if (i0 + u >= n4) break;
        __nv_bfloat16 h0, h1, h2, h3, l0, l1, l2, l3;
        split2(f[u].x, h0, l0); split2(f[u].y, h1, l1);
        split2(f[u].z, h2, l2); split2(f[u].w, h3, l3);
        __nv_bfloat162 hp0(h0, h1), hp1(h2, h3), lp0(l0, l1), lp1(l2, l3);
        uint2 hv, lv;
        hv.x = *(uint32_t*)&hp0; hv.y = *(uint32_t*)&hp1;
        lv.x = *(uint32_t*)&lp0; lv.y = *(uint32_t*)&lp1;
        ((uint2*)hi)[i0 + u] = hv;
        ((uint2*)lo)[i0 + u] = lv;
    }
}

// ---------------------------------------------------------------------------
// Split-bf16 warp-MMA GEMM — now 2 CTAs/SM (smem 80KB/CTA, regs capped 127)
// ---------------------------------------------------------------------------
#define ASTR   80
#define ABUF   (128*ASTR)
#define STAGE  (4*ABUF)
#define NCH    (DIMK/32)

__global__ __launch_bounds__(256, 2) void gemm_bf16x3(
    const __nv_bfloat16* __restrict__ Ah, const __nv_bfloat16* __restrict__ Al,
    const __nv_bfloat16* __restrict__ Bh, const __nv_bfloat16* __restrict__ Bl,
    float* __restrict__ C, int ldc, const float* __restrict__ bias)
{
    extern __shared__ char smem[];
    const uint32_t sb = smem_u32(smem);
    const int t = threadIdx.x;
    const int m0 = blockIdx.x * 128;
    const int n0 = blockIdx.y * 128;

    const int lane = t & 31;
    const int w    = t >> 5;
    const int wm   = w & 1;
    const int wn   = w >> 1;

    const __nv_bfloat16* gsrc[4] = {
        Ah + (size_t)m0 * DIMK, Al + (size_t)m0 * DIMK,
        Bh + (size_t)n0 * DIMK, Bl + (size_t)n0 * DIMK };

    auto load_chunk = [&](int c) {
        const int k0 = c * 32;
        const uint32_t stg = sb + (uint32_t)(c & 1) * STAGE;
#pragma unroll
        for (int pass = 0; pass < 8; pass++) {
            int seg = pass * 256 + t;
            int buf = seg >> 9;
            int idx = seg & 511;
            int row = idx >> 2;
            int c16 = idx & 3;
            const void* g = gsrc[buf] + (size_t)row * DIMK + k0 + c16 * 8;
            cp16(stg + buf * ABUF + row * ASTR + c16 * 16, g);
        }
        cp_commit();
    };

    const uint32_t a_off = (uint32_t)((lane & 15) * ASTR + (lane >> 4) * 16);
    const uint32_t b_off = (uint32_t)(((lane & 7) + ((lane >> 4) << 3)) * ASTR
                                      + (((lane >> 3) & 1) << 4));

    float acc[4][4][4];
#pragma unroll
    for (int i = 0; i < 4; i++)
#pragma unroll
        for (int j = 0; j < 4; j++)
#pragma unroll
            for (int r = 0; r < 4; r++) acc[i][j][r] = 0.f;

    load_chunk(0);

    for (int c = 0; c < NCH; c++) {
        if (c + 1 < NCH) {
            load_chunk(c + 1);
            cp_wait<1>();
        } else {
            cp_wait<0>();
        }
        __syncthreads();

        const uint32_t stg = sb + (uint32_t)(c & 1) * STAGE;
        const uint32_t aH = stg + 0 * ABUF + (uint32_t)(wm * 64) * ASTR + a_off;
        const uint32_t aL = stg + 1 * ABUF + (uint32_t)(wm * 64) * ASTR + a_off;
        const uint32_t bH = stg + 2 * ABUF + (uint32_t)(wn * 32) * ASTR + b_off;
        const uint32_t bL = stg + 3 * ABUF + (uint32_t)(wn * 32) * ASTR + b_off;

#pragma unroll
        for (int ks = 0; ks < 2; ks++) {
            const uint32_t ko = (uint32_t)(ks * 32);
            uint32_t ah[4][4], al[4][4];
#pragma unroll
            for (int mt = 0; mt < 4; mt++) {
                ldm4(ah[mt], aH + (uint32_t)(mt * 16) * ASTR + ko);
                ldm4(al[mt], aL + (uint32_t)(mt * 16) * ASTR + ko);
            }
            uint32_t bh[2][4], bl[2][4];
#pragma unroll
            for (int np = 0; np < 2; np++) {
                ldm4(bh[np], bH + (uint32_t)(np * 16) * ASTR + ko);
                ldm4(bl[np], bL + (uint32_t)(np * 16) * ASTR + ko);
            }
#pragma unroll
            for (int mt = 0; mt < 4; mt++) {
#pragma unroll
                for (int nt = 0; nt < 4; nt++) {
                    const uint32_t* ph = &bh[nt >> 1][(nt & 1) * 2];
                    const uint32_t* pl = &bl[nt >> 1][(nt & 1) * 2];
                    mma16816(acc[mt][nt], ah[mt], ph[0], ph[1]);
                    mma16816(acc[mt][nt], ah[mt], pl[0], pl[1]);
                    mma16816(acc[mt][nt], al[mt], ph[0], ph[1]);
                }
            }
        }
        __syncthreads();
    }

    const int g  = lane >> 2;
    const int tg = lane & 3;
#pragma unroll
    for (int mt = 0; mt < 4; mt++) {
        const int m = m0 + wm * 64 + mt * 16 + g;
#pragma unroll
        for (int nt = 0; nt < 4; nt++) {
            const int n = n0 + wn * 32 + nt * 8 + tg * 2;
            float b0 = 0.f, b1 = 0.f;
            if (bias) { b0 = bias[n]; b1 = bias[n + 1]; }
            float2 v0, v1;
            v0.x = acc[mt][nt][0] + b0; v0.y = acc[mt][nt][1] + b1;
            v1.x = acc[mt][nt][2] + b0; v1.y = acc[mt][nt][3] + b1;
            *(float2*)(C + (size_t)m * ldc + n) = v0;
            *(float2*)(C + (size_t)(m + 8) * ldc + n) = v1;
        }
    }
}

// ---------------------------------------------------------------------------
// Tensor-core block attention: one CTA per (b, blk, h), 9 warps (288 thr).
// ---------------------------------------------------------------------------
#define QKSTR   144
#define VPSTR   304
#define AQH     0
#define AQL     20736
#define AKH     41472
#define AKL     62208
#define AVH     82944
#define AVL     102400
#define APH     121856
#define APL     165632
#define ALSUM   209408
#define ATT_SMEM 209984

__global__ __launch_bounds__(288, 1) void attn_mma_kernel()
{
    extern __shared__ char smem[];
    const uint32_t sb = smem_u32(smem);
    const int tid = threadIdx.x;

    const int bid = blockIdx.x;
    const int h   = bid & 15;
    const int blk = (bid >> 4) & 31;
    const int b   = bid >> 9;
    const size_t rowbase = (size_t)b * NLEN + (size_t)blk * BLK;
    const float* base = g_qkv + rowbase * QKV_LD + h * DHEAD;

    for (int i = tid; i < 15 * 36; i += 288) {
        uint32_t off = (uint32_t)(129 + i / 36) * QKSTR + (uint32_t)(i % 36) * 4;
        *(uint32_t*)(smem + AQH + off) = 0;
        *(uint32_t*)(smem + AQL + off) = 0;
        *(uint32_t*)(smem + AKH + off) = 0;
        *(uint32_t*)(smem + AKL + off) = 0;
    }
    for (int i = tid; i < 64 * 15; i += 288) {
        uint32_t off = (uint32_t)(i / 15) * VPSTR + (uint32_t)(129 + i % 15) * 2;
        *(__nv_bfloat16*)(smem + AVH + off) = __float2bfloat16(0.f);
        *(__nv_bfloat16*)(smem + AVL + off) = __float2bfloat16(0.f);
    }

    for (int idx = tid; idx < BLK * 16; idx += 288) {
        const int j = idx >> 4, c = idx & 15;
        const float* p = base + (size_t)j * QKV_LD + c * 4;
        float4 q = *(const float4*)(p);
        float4 k = *(const float4*)(p + 1024);
        float4 v = *(const float4*)(p + 2048);
        q.x *= 0.125f; q.y *= 0.125f; q.z *= 0.125f; q.w *= 0.125f;
        __nv_bfloat16 qh[4], ql[4], kh[4], kl[4];
        split2(q.x, qh[0], ql[0]); split2(q.y, qh[1], ql[1]);
        split2(q.z, qh[2], ql[2]); split2(q.w, qh[3], ql[3]);
        split2(k.x, kh[0], kl[0]); split2(k.y, kh[1], kl[1]);
        split2(k.z, kh[2], kl[2]); split2(k.w, kh[3], kl[3]);
        uint32_t qrow = (uint32_t)j * QKSTR + (uint32_t)c * 8;
        *(__nv_bfloat162*)(smem + AQH + qrow)     = __nv_bfloat162(qh[0], qh[1]);
        *(__nv_bfloat162*)(smem + AQH + qrow + 4) = __nv_bfloat162(qh[2], qh[3]);
        *(__nv_bfloat162*)(smem + AQL + qrow)     = __nv_bfloat162(ql[0], ql[1]);
        *(__nv_bfloat162*)(smem + AQL + qrow + 4) = __nv_bfloat162(ql[2], ql[3]);
        *(__nv_bfloat162*)(smem + AKH + qrow)     = __nv_bfloat162(kh[0], kh[1]);
        *(__nv_bfloat162*)(smem + AKH + qrow + 4) = __nv_bfloat162(kh[2], kh[3]);
        *(__nv_bfloat162*)(smem + AKL + qrow)     = __nv_bfloat162(kl[0], kl[1]);
        *(__nv_bfloat162*)(smem + AKL + qrow + 4) = __nv_bfloat162(kl[2], kl[3]);
        float vv[4] = {v.x, v.y, v.z, v.w};
#pragma unroll
        for (int e = 0; e < 4; e++) {
            __nv_bfloat16 vh, vl;
            split2(vv[e], vh, vl);
            uint32_t off = (uint32_t)(c * 4 + e) * VPSTR + (uint32_t)j * 2;
            *(__nv_bfloat16*)(smem + AVH + off) = vh;
            *(__nv_bfloat16*)(smem + AVL + off) = vl;
        }
    }
    __syncthreads();

    const int w    = tid >> 5;
    const int lane = tid & 31;
    const int tg   = lane & 3;
    const int gr   = lane >> 2;

    float acc[18][4];
#pragma unroll
    for (int i = 0; i < 18; i++)
#pragma unroll
        for (int r = 0; r < 4; r++) acc[i][r] = 0.f;

    const uint32_t aoff = (uint32_t)((lane & 15) * QKSTR + (lane >> 4) * 16)
                        + (uint32_t)(w * 16) * QKSTR;
    const uint32_t bro  = (uint32_t)((lane & 7) + ((lane >> 4) << 3));
    const uint32_t bko  = (uint32_t)(((lane >> 3) & 1) << 4);

#pragma unroll
    for (int ko = 0; ko < 4; ko++) {
        uint32_t ah[4], al[4];
        ldm4(ah, sb + AQH + aoff + ko * 32);
        ldm4(al, sb + AQL + aoff + ko * 32);
#pragma unroll
        for (int np = 0; np < 9; np++) {
            uint32_t boff = ((uint32_t)(np * 16) + bro) * QKSTR + bko + ko * 32;
            uint32_t bh[4], bl[4];
            ldm4(bh, sb + AKH + boff);
            ldm4(bl, sb + AKL + boff);
#pragma unroll
            for (int q2 = 0; q2 < 2; q2++) {
                float* a0 = acc[np * 2 + q2];
                mma16816(a0, ah, bh[q2 * 2], bh[q2 * 2 + 1]);
                mma16816(a0, ah, bl[q2 * 2], bl[q2 * 2 + 1]);
                mma16816(a0, al, bh[q2 * 2], bh[q2 * 2 + 1]);
            }
        }
    }

    const int r0 = w * 16 + gr;
    const int r1 = r0 + 8;
    float m0 = -1e30f, m1 = -1e30f;
#pragma unroll
    for (int nt = 0; nt < 18; nt++) {
        int col = nt * 8 + tg * 2;
        if (col < 129)     { m0 = fmaxf(m0, acc[nt][0]); m1 = fmaxf(m1, acc[nt][2]); }
        if (col + 1 < 129) { m0 = fmaxf(m0, acc[nt][1]); m1 = fmaxf(m1, acc[nt][3]); }
    }
    m0 = fmaxf(m0, __shfl_xor_sync(0xffffffff, m0, 1));
    m0 = fmaxf(m0, __shfl_xor_sync(0xffffffff, m0, 2));
    m1 = fmaxf(m1, __shfl_xor_sync(0xffffffff, m1, 1));
    m1 = fmaxf(m1, __shfl_xor_sync(0xffffffff, m1, 2));

    float l0 = 0.f, l1 = 0.f;
#pragma unroll
    for (int nt = 0; nt < 18; nt++) {
        int col = nt * 8 + tg * 2;
        acc[nt][0] = (col < 129)     ? __expf(acc[nt][0] - m0) : 0.f;
        acc[nt][1] = (col + 1 < 129) ? __expf(acc[nt][1] - m0) : 0.f;
        acc[nt][2] = (col < 129)     ? __expf(acc[nt][2] - m1) : 0.f;
        acc[nt][3] = (col + 1 < 129) ? __expf(acc[nt][3] - m1) : 0.f;
        l0 += acc[nt][0] + acc[nt][1];
        l1 += acc[nt][2] + acc[nt][3];
    }
    l0 += __shfl_xor_sync(0xffffffff, l0, 1);
    l0 += __shfl_xor_sync(0xffffffff, l0, 2);
    l1 += __shfl_xor_sync(0xffffffff, l1, 1);
    l1 += __shfl_xor_sync(0xffffffff, l1, 2);
    if (tg == 0) {
        *(float*)(smem + ALSUM + r0 * 4) = l0;
        *(float*)(smem + ALSUM + r1 * 4) = l1;
    }

#pragma unroll
    for (int nt = 0; nt < 18; nt++) {
        int col = nt * 8 + tg * 2;
        __nv_bfloat16 h0, h1, h2, h3, e0, e1, e2, e3;
        split2(acc[nt][0], h0, e0); split2(acc[nt][1], h1, e1);
        split2(acc[nt][2], h2, e2); split2(acc[nt][3], h3, e3);
        uint32_t o0 = (uint32_t)r0 * VPSTR + (uint32_t)col * 2;
        uint32_t o1 = (uint32_t)r1 * VPSTR + (uint32_t)col * 2;
        *(__nv_bfloat162*)(smem + APH + o0) = __nv_bfloat162(h0, h1);
        *(__nv_bfloat162*)(smem + APH + o1) = __nv_bfloat162(h2, h3);
        *(__nv_bfloat162*)(smem + APL + o0) = __nv_bfloat162(e0, e1);
        *(__nv_bfloat162*)(smem + APL + o1) = __nv_bfloat162(e2, e3);
    }
    __syncwarp();

    float o[8][4];
#pragma unroll
    for (int i = 0; i < 8; i++)
#pragma unroll
        for (int r = 0; r < 4; r++) o[i][r] = 0.f;

    const uint32_t paoff = (uint32_t)((lane & 15) * VPSTR + (lane >> 4) * 16)
                         + (uint32_t)(w * 16) * VPSTR;
#pragma unroll
    for (int ko = 0; ko < 9; ko++) {
        uint32_t ph[4], pl[4];
        ldm4(ph, sb + APH + paoff + ko * 32);
        ldm4(pl, sb + APL + paoff + ko * 32);
#pragma unroll
        for (int np = 0; np < 4; np++) {
            uint32_t boff = ((uint32_t)(np * 16) + bro) * VPSTR + bko + ko * 32;
            uint32_t vh[4], vl[4];
            ldm4(vh, sb + AVH + boff);
            ldm4(vl, sb + AVL + boff);
#pragma unroll
            for (int q2 = 0; q2 < 2; q2++) {
                float* d0 = o[np * 2 + q2];
                mma16816(d0, ph, vh[q2 * 2], vh[q2 * 2 + 1]);
                mma16816(d0, ph, vl[q2 * 2], vl[q2 * 2 + 1]);
                mma16816(d0, pl, vh[q2 * 2], vh[q2 * 2 + 1]);
            }
        }
    }

    const float* gadd = g_gout + ((size_t)(b * 16 + h) * 32 + blk) * 64;
    const float inv0 = 1.f / *(float*)(smem + ALSUM + r0 * 4);
    const float inv1 = 1.f / *(float*)(smem + ALSUM + r1 * 4);
#pragma unroll
    for (int nt = 0; nt < 8; nt++) {
        int col = nt * 8 + tg * 2;
        if (r0 < 129) {
            float v0 = o[nt][0] * inv0;
            float v1 = o[nt][1] * inv0;
            if (r0 == 0) { v0 += gadd[col]; v1 += gadd[col + 1]; }
            __nv_bfloat16 h0, h1, e0, e1;
            split2(v0, h0, e0); split2(v1, h1, e1);
            size_t go = (rowbase + r0) * DIMK + h * DHEAD + col;
            *(__nv_bfloat162*)(g_ath + go) = __nv_bfloat162(h0, h1);
            *(__nv_bfloat162*)(g_atl + go) = __nv_bfloat162(e0, e1);
        }
        if (r1 < 129) {
            float v0 = o[nt][2] * inv1;
            float v1 = o[nt][3] * inv1;
            __nv_bfloat16 h0, h1, e0, e1;
            split2(v0, h0, e0); split2(v1, h1, e1);
            size_t go = (rowbase + r1) * DIMK + h * DHEAD + col;
            *(__nv_bfloat162*)(g_ath + go) = __nv_bfloat162(h0, h1);
            *(__nv_bfloat162*)(g_atl + go) = __nv_bfloat162(e0, e1);
        }
    }
}

// ---------------------------------------------------------------------------
// Global leader attention: writes g_gout (runs BEFORE attn_mma_kernel)
// ---------------------------------------------------------------------------
__global__ __launch_bounds__(64) void gattn_kernel()
{
    __shared__ float Kg[NB * 64];
    __shared__ float Vg[NB * 64];

    const int b = blockIdx.x >> 4;
    const int h = blockIdx.x & 15;
    const int tid = threadIdx.x;

    const float* base = g_qkv + (size_t)b * NLEN * QKV_LD + h * DHEAD;

    for (int idx = tid; idx < NB * 16; idx += 64) {
        int j = idx >> 4, c = idx & 15;
        const float* p = base + (size_t)j * BLK * QKV_LD + c * 4;
        *(float4*)(Kg + j*64 + c*4) = *(const float4*)(p + 1024);
        *(float4*)(Vg + j*64 + c*4) = *(const float4*)(p + 2048);
    }
    __syncthreads();

    if (tid < NB) {
        const float* qp = base + (size_t)tid * BLK * QKV_LD;
        float q[64];
#pragma unroll
        for (int c = 0; c < 16; c++) {
            float4 f = *(const float4*)(qp + c*4);
            q[c*4+0]=f.x; q[c*4+1]=f.y; q[c*4+2]=f.z; q[c*4+3]=f.w;
        }

        float s[NB];
        float mmax = -1e30f;
#pragma unroll
        for (int j = 0; j < NB; j++) {
            const float* kj = Kg + j * 64;
            float a0=0.f, a1=0.f, a2=0.f, a3=0.f;
#pragma unroll
            for (int d = 0; d < 64; d += 4) {
                a0 += q[d+0]*kj[d+0]; a1 += q[d+1]*kj[d+1];
                a2 += q[d+2]*kj[d+2]; a3 += q[d+3]*kj[d+3];
            }
            float sv = ((a0+a1)+(a2+a3)) * 0.125f;
            s[j] = sv;
            mmax = fmaxf(mmax, sv);
        }
        float l = 0.f;
#pragma unroll
        for (int j = 0; j < NB; j++) { s[j] = __expf(s[j]-mmax); l += s[j]; }
        float inv = 1.f / l;

        float acc[64];
#pragma unroll
        for (int d = 0; d < 64; d++) acc[d] = 0.f;
#pragma unroll
        for (int j = 0; j < NB; j++) {
            float p = s[j];
            const float* vj = Vg + j * 64;
#pragma unroll
            for (int d = 0; d < 64; d++) acc[d] += p * vj[d];
        }

        float* op = g_gout + ((size_t)(b * 16 + h) * 32 + tid) * 64;
#pragma unroll
        for (int d = 0; d < 64; d++) op[d] = acc[d] * inv;
    }
}

// ---------------------------------------------------------------------------
extern "C" void kernel_launch(void* const* d_in, const int* in_sizes, int n_in,
                              void* d_out, int out_size)
{
    (void)in_sizes; (void)n_in; (void)out_size;
    const float* x  = (const float*)d_in[0];
    const float* Wq = (const float*)d_in[1];
    const float* Wk = (const float*)d_in[2];
    const float* Wv = (const float*)d_in[3];
    const float* Wo = (const float*)d_in[4];
    const float* bo = (const float*)d_in[5];
    float* out = (float*)d_out;

    float* qkv;
    __nv_bfloat16 *xh, *xl, *wh, *wl, *woh, *wol, *ath, *atl;
    cudaGetSymbolAddress((void**)&qkv, g_qkv);
    cudaGetSymbolAddress((void**)&xh, g_xh);
    cudaGetSymbolAddress((void**)&xl, g_xl);
    cudaGetSymbolAddress((void**)&wh, g_wh);
    cudaGetSymbolAddress((void**)&wl, g_wl);
    cudaGetSymbolAddress((void**)&woh, g_woh);
    cudaGetSymbolAddress((void**)&wol, g_wol);
    cudaGetSymbolAddress((void**)&ath, g_ath);
    cudaGetSymbolAddress((void**)&atl, g_atl);

    static int s_init = 0;
    if (!s_init) {
        cudaFuncSetAttribute(gemm_bf16x3,
            cudaFuncAttributeMaxDynamicSharedMemorySize, 2 * STAGE);
        cudaFuncSetAttribute(attn_mma_kernel,
            cudaFuncAttributeMaxDynamicSharedMemorySize, ATT_SMEM);
        s_init = 1;
    }

    // fp32 -> bf16 hi/lo splits
    {
        int n4x = ROWS * DIMK / 4;
        cvt_kernel<<<(n4x + 1023) / 1024, 256>>>(x, xh, xl, n4x);
        int n4w = DIMK * DIMK / 4;
        cvt_kernel<<<(n4w + 1023) / 1024, 256>>>(Wq, wh, wl, n4w);
        cvt_kernel<<<(n4w + 1023) / 1024, 256>>>(Wk, wh + (size_t)1024 * DIMK,
                                                 wl + (size_t)1024 * DIMK, n4w);
        cvt_kernel<<<(n4w + 1023) / 1024, 256>>>(Wv, wh + (size_t)2048 * DIMK,
                                                 wl + (size_t)2048 * DIMK, n4w);
        cvt_kernel<<<(n4w + 1023) / 1024, 256>>>(Wo, woh, wol, n4w);
    }

    // 1) QKV projection
    {
        dim3 grid(ROWS / 128, QKV_LD / 128);
        gemm_bf16x3<<<grid, 256, 2 * STAGE>>>(xh, xl, wh, wl, qkv, QKV_LD, nullptr);
    }

    // 2) global leader attention (before block attention)
    gattn_kernel<<<BATCH * HEADS, 64>>>();

    // 3) block-local attention (tensor cores), writes split bf16 directly
    attn_mma_kernel<<<BATCH * NB * HEADS, 288, ATT_SMEM>>>();

    // 4) output projection + bias
    {
        dim3 grid(ROWS / 128, DIMK / 128);
        gemm_bf16x3<<<grid, 256, 2 * STAGE>>>(ath, atl, woh, wol, out, DIMK, bo);
    }
}